// round 1
// baseline (speedup 1.0000x reference)
#include <cuda_runtime.h>
#include <math.h>

#define NP 128
#define ND 3
#define DIM (NP*ND)
#define FF 32
#define HH 32
#define BB 128
#define NEDGE (NP*(NP-1))   // 16256
#define NNODE (BB*NP)       // 16384

// scratch (static device arrays, no allocation)
__device__ float g_A [NNODE*FF];   // h_i @ W_hi + e_b1
__device__ float g_Bm[NNODE*FF];   // h_j @ W_hj
__device__ float g_mi[NNODE*FF];   // per-node summed messages

__device__ __forceinline__ float sigf(float v) {
    return __fdividef(1.0f, 1.0f + __expf(-v));
}
__device__ __forceinline__ float siluf(float v) {
    return v * sigf(v);
}

// ---------------------------------------------------------------------------
// Kernel 0: per-node precompute A = h@W_hi + e_b1, Bm = h@W_hj
// warp per node, lane = output feature f
// ---------------------------------------------------------------------------
__global__ __launch_bounds__(128) void prenode_kernel(
    const float* __restrict__ h, const float* __restrict__ e_w1,
    const float* __restrict__ e_b1)
{
    int node = blockIdx.x * 4 + (threadIdx.x >> 5);
    int f    = threadIdx.x & 31;
    float hv = h[node*FF + f];
    float a  = e_b1[f];
    float bm = 0.0f;
#pragma unroll
    for (int k = 0; k < FF; k++) {
        float hk = __shfl_sync(0xffffffffu, hv, k);
        a  += hk * e_w1[k*HH + f];          // rows 0..31  : hi part
        bm += hk * e_w1[(FF + k)*HH + f];   // rows 32..63 : hj part
    }
    g_A [node*FF + f] = a;
    g_Bm[node*FF + f] = bm;
}

// ---------------------------------------------------------------------------
// Kernel 1: edge MLP. Block = (b, i). Thread j = 0..127 handles edge (i->j).
// ---------------------------------------------------------------------------
__global__ __launch_bounds__(128, 4) void edge_kernel(
    const float* __restrict__ x,      const float* __restrict__ d_static,
    const float* __restrict__ e_w1,   const float* __restrict__ e_w2,
    const float* __restrict__ e_b2,   const float* __restrict__ c_w1,
    const float* __restrict__ c_b1,   const float* __restrict__ c_w2,
    const float* __restrict__ a_w,    const float* __restrict__ a_b,
    float* __restrict__ x_out)
{
    __shared__ __align__(16) float s_w2[FF*HH];     // e_w2 (32x32)
    __shared__ __align__(16) float s_c1[FF*HH];     // c_w1 (32x32)
    __shared__ __align__(16) float s_misc[7*32];    // wd,wds,eb2,cb1,aw,cw2,Ai
    __shared__ __align__(16) float s_red[32*129];   // padded reduction buffer
    __shared__ float s_part[4][32];
    __shared__ float s_xp[4][3];
    __shared__ float s_xi[3];
    __shared__ float s_ab;

    const int t = threadIdx.x;
    const int bi = blockIdx.x;
    const int b = bi >> 7;
    const int i = bi & 127;
    const int j = t;
    const int lane = t & 31;
    const int warp = t >> 5;

    for (int idx = t; idx < FF*HH; idx += 128) {
        s_w2[idx] = e_w2[idx];
        s_c1[idx] = c_w1[idx];
    }
    if (t < 32) {
        s_misc[t        ] = e_w1[(2*FF    )*HH + t];  // w_d
        s_misc[32  + t  ] = e_w1[(2*FF + 1)*HH + t];  // w_ds
        s_misc[64  + t  ] = e_b2[t];
        s_misc[96  + t  ] = c_b1[t];
        s_misc[128 + t  ] = a_w[t];
        s_misc[160 + t  ] = c_w2[t];
        s_misc[192 + t  ] = g_A[(b*NP + i)*FF + t];
    }
    if (t == 0) s_ab = a_b[0];
    if (t < 3)  s_xi[t] = x[b*DIM + i*ND + t];
    __syncthreads();

    // ---- edge geometry ----
    float xjx = x[b*DIM + j*ND + 0];
    float xjy = x[b*DIM + j*ND + 1];
    float xjz = x[b*DIM + j*ND + 2];
    float rx = s_xi[0] - xjx;
    float ry = s_xi[1] - xjy;
    float rz = s_xi[2] - xjz;
    float d2 = rx*rx + ry*ry + rz*rz;
    float d  = sqrtf(d2 + 1e-6f);

    int e = i*(NP-1) + (j < i ? j : j-1);
    if (j == i) e = 0;
    float ds  = d_static[b*NEDGE + e];
    float ds2 = ds*ds;

    // ---- layer 1: A_i + Bm_j + d^2*w_d + ds^2*w_ds, then silu ----
    float s1[FF];
    {
        const float4* Bj = (const float4*)(g_Bm + (b*NP + j)*FF);
#pragma unroll
        for (int k = 0; k < FF; k += 4) {
            float4 bv = Bj[k >> 2];
            s1[k+0] = s_misc[192+k+0] + bv.x + d2*s_misc[k+0] + ds2*s_misc[32+k+0];
            s1[k+1] = s_misc[192+k+1] + bv.y + d2*s_misc[k+1] + ds2*s_misc[32+k+1];
            s1[k+2] = s_misc[192+k+2] + bv.z + d2*s_misc[k+2] + ds2*s_misc[32+k+2];
            s1[k+3] = s_misc[192+k+3] + bv.w + d2*s_misc[k+3] + ds2*s_misc[32+k+3];
        }
    }
#pragma unroll
    for (int k = 0; k < FF; k++) s1[k] = siluf(s1[k]);

    // ---- layer 2: m = silu(s1 @ e_w2 + e_b2) ----
    float m[FF];
#pragma unroll
    for (int f = 0; f < FF; f++) m[f] = s_misc[64 + f];
#pragma unroll
    for (int k = 0; k < FF; k++) {
        float s = s1[k];
        const float* w = s_w2 + k*HH;
#pragma unroll
        for (int f = 0; f < FF; f++) m[f] += s * w[f];
    }
#pragma unroll
    for (int f = 0; f < FF; f++) m[f] = siluf(m[f]);

    // ---- attention gate: m *= sigmoid(m @ a_w + a_b) ----
    float att = s_ab;
#pragma unroll
    for (int f = 0; f < FF; f++) att += m[f] * s_misc[128 + f];
    att = sigf(att);
#pragma unroll
    for (int f = 0; f < FF; f++) m[f] *= att;

    // ---- coord head: trans = tanh(silu(m @ c_w1 + c_b1) @ c_w2) ----
    float c1[HH];
#pragma unroll
    for (int k = 0; k < HH; k++) c1[k] = s_misc[96 + k];
#pragma unroll
    for (int f = 0; f < FF; f++) {
        float mf = m[f];
        const float* w = s_c1 + f*HH;
#pragma unroll
        for (int k = 0; k < HH; k++) c1[k] += mf * w[k];
    }
    float trans = 0.0f;
#pragma unroll
    for (int k = 0; k < HH; k++) trans += siluf(c1[k]) * s_misc[160 + k];
    trans = tanhf(trans);

    float valid = (j == i) ? 0.0f : 1.0f;
    float coef = valid * __fdividef(trans, d + 1.0f);
#pragma unroll
    for (int f = 0; f < FF; f++) m[f] *= valid;

    // ---- reduce coord update across the 128 threads (warp bfly + smem) ----
    float xc0 = rx*coef, xc1 = ry*coef, xc2 = rz*coef;
#pragma unroll
    for (int off = 16; off > 0; off >>= 1) {
        xc0 += __shfl_xor_sync(0xffffffffu, xc0, off);
        xc1 += __shfl_xor_sync(0xffffffffu, xc1, off);
        xc2 += __shfl_xor_sync(0xffffffffu, xc2, off);
    }
    if (lane == 0) { s_xp[warp][0] = xc0; s_xp[warp][1] = xc1; s_xp[warp][2] = xc2; }

    // ---- reduce m over 128 threads: column-major padded smem (stride 129) ----
#pragma unroll
    for (int c = 0; c < FF; c++) s_red[c*129 + j] = m[c];
    __syncthreads();

    {   // thread t sums quarter q of feature f:  bank = (f + j) % 32 -> conflict-free
        int f = t & 31, q = t >> 5;
        float acc = 0.0f;
#pragma unroll
        for (int n = 0; n < 32; n++) acc += s_red[f*129 + q*32 + n];
        s_part[q][f] = acc;
    }
    __syncthreads();

    if (t < 32) {
        float mi = s_part[0][t] + s_part[1][t] + s_part[2][t] + s_part[3][t];
        g_mi[(b*NP + i)*FF + t] = mi;
    }
    if (t < 3) {
        float xs = s_xp[0][t] + s_xp[1][t] + s_xp[2][t] + s_xp[3][t];
        x_out[b*DIM + i*ND + t] = s_xi[t] + xs * 5.0f;   // COORDS_RANGE
    }
}

// ---------------------------------------------------------------------------
// Kernel 2: node update MLP.  warp per node, lane = feature f.
// ---------------------------------------------------------------------------
__global__ __launch_bounds__(128) void node_kernel(
    const float* __restrict__ h,
    const float* __restrict__ n_w1, const float* __restrict__ n_b1,
    const float* __restrict__ n_w2, const float* __restrict__ n_b2,
    float* __restrict__ h_out)
{
    int node = blockIdx.x * 4 + (threadIdx.x >> 5);
    int f    = threadIdx.x & 31;
    float hv = h[node*FF + f];
    float mv = g_mi[node*FF + f];
    float acc = n_b1[f];
#pragma unroll
    for (int k = 0; k < FF; k++)
        acc += __shfl_sync(0xffffffffu, hv, k) * n_w1[k*HH + f];
#pragma unroll
    for (int k = 0; k < FF; k++)
        acc += __shfl_sync(0xffffffffu, mv, k) * n_w1[(FF + k)*HH + f];
    float tt = siluf(acc);
    float acc2 = n_b2[f];
#pragma unroll
    for (int k = 0; k < HH; k++)
        acc2 += __shfl_sync(0xffffffffu, tt, k) * n_w2[k*FF + f];
    h_out[node*FF + f] = hv + acc2;
}

// ---------------------------------------------------------------------------
extern "C" void kernel_launch(void* const* d_in, const int* in_sizes, int n_in,
                              void* d_out, int out_size)
{
    const float* x        = (const float*)d_in[0];
    const float* h        = (const float*)d_in[1];
    const float* d_static = (const float*)d_in[2];
    const float* e_w1     = (const float*)d_in[3];
    const float* e_b1     = (const float*)d_in[4];
    const float* e_w2     = (const float*)d_in[5];
    const float* e_b2     = (const float*)d_in[6];
    const float* n_w1     = (const float*)d_in[7];
    const float* n_b1     = (const float*)d_in[8];
    const float* n_w2     = (const float*)d_in[9];
    const float* n_b2     = (const float*)d_in[10];
    const float* c_w1     = (const float*)d_in[11];
    const float* c_b1     = (const float*)d_in[12];
    const float* c_w2     = (const float*)d_in[13];
    const float* a_w      = (const float*)d_in[14];
    const float* a_b      = (const float*)d_in[15];

    float* out   = (float*)d_out;
    float* x_out = out;                 // B*DIM floats
    float* h_out = out + BB*DIM;        // B*NP*FF floats

    prenode_kernel<<<NNODE/4, 128>>>(h, e_w1, e_b1);
    edge_kernel<<<BB*NP, 128>>>(x, d_static, e_w1, e_w2, e_b2,
                                c_w1, c_b1, c_w2, a_w, a_b, x_out);
    node_kernel<<<NNODE/4, 128>>>(h, n_w1, n_b1, n_w2, n_b2, h_out);
}

// round 2
// speedup vs baseline: 2.1333x; 2.1333x over previous
#include <cuda_runtime.h>
#include <math.h>

#define NP 128
#define ND 3
#define DIM (NP*ND)
#define FF 32
#define HH 32
#define BB 128
#define NEDGE (NP*(NP-1))   // 16256
#define NNODE (BB*NP)       // 16384

// scratch (static device arrays, no allocation)
__device__ float g_A [NNODE*FF];   // h_i @ W_hi + e_b1
__device__ float g_Bm[NNODE*FF];   // h_j @ W_hj
__device__ float g_mi[NNODE*FF];   // per-node summed messages

// ---- packed f32x2 helpers (FFMA2: only reachable via PTX on sm_103a) ----
#define FMA2(d,a,b,c) asm("fma.rn.f32x2 %0, %1, %2, %3;" : "=l"(d) : "l"(a), "l"(b), "l"(c))
#define ADD2(d,a,b)   asm("add.rn.f32x2 %0, %1, %2;"     : "=l"(d) : "l"(a), "l"(b))
#define PACK2(d,lo,hi) asm("mov.b64 %0, {%1, %2};" : "=l"(d) : "f"(lo), "f"(hi))
#define UNPK2(lo,hi,s) asm("mov.b64 {%0, %1}, %2;" : "=f"(lo), "=f"(hi) : "l"(s))

typedef unsigned long long u64;

__device__ __forceinline__ float sigf(float v) {
    return __fdividef(1.0f, 1.0f + __expf(-v));
}
__device__ __forceinline__ float siluf(float v) {
    return __fdividef(v, 1.0f + __expf(-v));
}

// ---------------------------------------------------------------------------
// Kernel 0: per-node precompute A = h@W_hi + e_b1, Bm = h@W_hj
// ---------------------------------------------------------------------------
__global__ __launch_bounds__(128) void prenode_kernel(
    const float* __restrict__ h, const float* __restrict__ e_w1,
    const float* __restrict__ e_b1)
{
    int node = blockIdx.x * 4 + (threadIdx.x >> 5);
    int f    = threadIdx.x & 31;
    float hv = h[node*FF + f];
    float a  = e_b1[f];
    float bm = 0.0f;
#pragma unroll
    for (int k = 0; k < FF; k++) {
        float hk = __shfl_sync(0xffffffffu, hv, k);
        a  += hk * e_w1[k*HH + f];          // rows 0..31  : hi part
        bm += hk * e_w1[(FF + k)*HH + f];   // rows 32..63 : hj part
    }
    g_A [node*FF + f] = a;
    g_Bm[node*FF + f] = bm;
}

// ---------------------------------------------------------------------------
// Kernel 1: edge MLP. Block = (b, i). Thread j = 0..127 handles edge (i->j).
// All 32x32 GEMVs run on packed f32x2 (feature pairs); weights arrive packed
// for free via LDS.128 (ulonglong2).
// ---------------------------------------------------------------------------
__global__ __launch_bounds__(128) void edge_kernel(
    const float* __restrict__ x,      const float* __restrict__ d_static,
    const float* __restrict__ e_w1,   const float* __restrict__ e_w2,
    const float* __restrict__ e_b2,   const float* __restrict__ c_w1,
    const float* __restrict__ c_b1,   const float* __restrict__ c_w2,
    const float* __restrict__ a_w,    const float* __restrict__ a_b,
    float* __restrict__ x_out)
{
    __shared__ __align__(16) float s_w2[FF*HH];     // e_w2 (32x32)
    __shared__ __align__(16) float s_c1[FF*HH];     // c_w1 (32x32)
    __shared__ __align__(16) float s_misc[7*32];    // wd,wds,eb2,cb1,aw,cw2,Ai
    __shared__ __align__(16) float s_red[32*129];   // padded reduction buffer
    __shared__ float s_part[4][32];
    __shared__ float s_xp[4][3];
    __shared__ float s_xi[3];
    __shared__ float s_ab;

    const int t = threadIdx.x;
    const int bi = blockIdx.x;
    const int b = bi >> 7;
    const int i = bi & 127;
    const int j = t;
    const int lane = t & 31;
    const int warp = t >> 5;

    for (int idx = t; idx < FF*HH; idx += 128) {
        s_w2[idx] = e_w2[idx];
        s_c1[idx] = c_w1[idx];
    }
    if (t < 32) {
        s_misc[t        ] = e_w1[(2*FF    )*HH + t];  // w_d
        s_misc[32  + t  ] = e_w1[(2*FF + 1)*HH + t];  // w_ds
        s_misc[64  + t  ] = e_b2[t];
        s_misc[96  + t  ] = c_b1[t];
        s_misc[128 + t  ] = a_w[t];
        s_misc[160 + t  ] = c_w2[t];
        s_misc[192 + t  ] = g_A[(b*NP + i)*FF + t];
    }
    if (t == 0) s_ab = a_b[0];
    if (t < 3)  s_xi[t] = x[b*DIM + i*ND + t];
    __syncthreads();

    // ---- edge geometry ----
    float xjx = x[b*DIM + j*ND + 0];
    float xjy = x[b*DIM + j*ND + 1];
    float xjz = x[b*DIM + j*ND + 2];
    float rx = s_xi[0] - xjx;
    float ry = s_xi[1] - xjy;
    float rz = s_xi[2] - xjz;
    float d2 = rx*rx + ry*ry + rz*rz;
    float d  = sqrtf(d2 + 1e-6f);

    int e = i*(NP-1) + (j < i ? j : j-1);
    if (j == i) e = 0;
    float ds  = d_static[b*NEDGE + e];
    float ds2 = ds*ds;

    // ---- layer 1 (packed): s1 = silu(A_i + Bm_j + d^2*w_d + ds^2*w_ds) ----
    float s1[FF];
    {
        u64 d2p, dsp;
        PACK2(d2p, d2, d2);
        PACK2(dsp, ds2, ds2);
        const ulonglong2* Bj  = (const ulonglong2*)(g_Bm + (b*NP + j)*FF);
        const ulonglong2* Ai  = (const ulonglong2*)(s_misc + 192);
        const ulonglong2* Wd  = (const ulonglong2*)(s_misc + 0);
        const ulonglong2* Wds = (const ulonglong2*)(s_misc + 32);
#pragma unroll
        for (int q = 0; q < 8; q++) {
            ulonglong2 bv = Bj[q], av = Ai[q], wdv = Wd[q], wsv = Wds[q];
            u64 t0, t1;
            ADD2(t0, av.x, bv.x);
            FMA2(t0, d2p, wdv.x, t0);
            FMA2(t0, dsp, wsv.x, t0);
            ADD2(t1, av.y, bv.y);
            FMA2(t1, d2p, wdv.y, t1);
            FMA2(t1, dsp, wsv.y, t1);
            UNPK2(s1[4*q+0], s1[4*q+1], t0);
            UNPK2(s1[4*q+2], s1[4*q+3], t1);
        }
    }
#pragma unroll
    for (int k = 0; k < FF; k++) s1[k] = siluf(s1[k]);

    // ---- layer 2 (packed): m = silu(s1 @ e_w2 + e_b2) ----
    float m[FF];
    {
        u64 m2[16];
        const ulonglong2* b2 = (const ulonglong2*)(s_misc + 64);
#pragma unroll
        for (int q = 0; q < 8; q++) { ulonglong2 v = b2[q]; m2[2*q] = v.x; m2[2*q+1] = v.y; }
#pragma unroll
        for (int k = 0; k < FF; k++) {
            u64 s2; PACK2(s2, s1[k], s1[k]);
            const ulonglong2* wr = (const ulonglong2*)(s_w2 + k*HH);
#pragma unroll
            for (int q = 0; q < 8; q++) {
                ulonglong2 wv = wr[q];
                FMA2(m2[2*q],   s2, wv.x, m2[2*q]);
                FMA2(m2[2*q+1], s2, wv.y, m2[2*q+1]);
            }
        }
#pragma unroll
        for (int q = 0; q < 16; q++) UNPK2(m[2*q], m[2*q+1], m2[q]);
    }
#pragma unroll
    for (int f = 0; f < FF; f++) m[f] = siluf(m[f]);

    // ---- attention gate: m *= sigmoid(m @ a_w + a_b) ----
    float att = s_ab;
#pragma unroll
    for (int f = 0; f < FF; f++) att += m[f] * s_misc[128 + f];
    att = sigf(att);
#pragma unroll
    for (int f = 0; f < FF; f++) m[f] *= att;

    // ---- coord head (packed): trans = tanh(silu(m @ c_w1 + c_b1) @ c_w2) ----
    float trans;
    {
        u64 c2[16];
        const ulonglong2* b2 = (const ulonglong2*)(s_misc + 96);
#pragma unroll
        for (int q = 0; q < 8; q++) { ulonglong2 v = b2[q]; c2[2*q] = v.x; c2[2*q+1] = v.y; }
#pragma unroll
        for (int f = 0; f < FF; f++) {
            u64 mp; PACK2(mp, m[f], m[f]);
            const ulonglong2* wr = (const ulonglong2*)(s_c1 + f*HH);
#pragma unroll
            for (int q = 0; q < 8; q++) {
                ulonglong2 wv = wr[q];
                FMA2(c2[2*q],   mp, wv.x, c2[2*q]);
                FMA2(c2[2*q+1], mp, wv.y, c2[2*q+1]);
            }
        }
        float acc = 0.0f;
#pragma unroll
        for (int q = 0; q < 16; q++) {
            float c0, c1v;
            UNPK2(c0, c1v, c2[q]);
            acc += siluf(c0)  * s_misc[160 + 2*q];
            acc += siluf(c1v) * s_misc[160 + 2*q + 1];
        }
        trans = tanhf(acc);
    }

    float valid = (j == i) ? 0.0f : 1.0f;
    float coef = valid * __fdividef(trans, d + 1.0f);
#pragma unroll
    for (int f = 0; f < FF; f++) m[f] *= valid;

    // ---- reduce coord update across the 128 threads (warp bfly + smem) ----
    float xc0 = rx*coef, xc1 = ry*coef, xc2 = rz*coef;
#pragma unroll
    for (int off = 16; off > 0; off >>= 1) {
        xc0 += __shfl_xor_sync(0xffffffffu, xc0, off);
        xc1 += __shfl_xor_sync(0xffffffffu, xc1, off);
        xc2 += __shfl_xor_sync(0xffffffffu, xc2, off);
    }
    if (lane == 0) { s_xp[warp][0] = xc0; s_xp[warp][1] = xc1; s_xp[warp][2] = xc2; }

    // ---- reduce m over 128 threads: column-major padded smem (stride 129) ----
#pragma unroll
    for (int c = 0; c < FF; c++) s_red[c*129 + j] = m[c];
    __syncthreads();

    {   // thread t sums quarter q of feature f:  bank = (f + j) % 32 -> conflict-free
        int f = t & 31, q = t >> 5;
        float acc = 0.0f;
#pragma unroll
        for (int n = 0; n < 32; n++) acc += s_red[f*129 + q*32 + n];
        s_part[q][f] = acc;
    }
    __syncthreads();

    if (t < 32) {
        float mi = s_part[0][t] + s_part[1][t] + s_part[2][t] + s_part[3][t];
        g_mi[(b*NP + i)*FF + t] = mi;
    }
    if (t < 3) {
        float xs = s_xp[0][t] + s_xp[1][t] + s_xp[2][t] + s_xp[3][t];
        x_out[b*DIM + i*ND + t] = s_xi[t] + xs * 5.0f;   // COORDS_RANGE
    }
}

// ---------------------------------------------------------------------------
// Kernel 2: node update MLP.  warp per node, lane = feature f.
// ---------------------------------------------------------------------------
__global__ __launch_bounds__(128) void node_kernel(
    const float* __restrict__ h,
    const float* __restrict__ n_w1, const float* __restrict__ n_b1,
    const float* __restrict__ n_w2, const float* __restrict__ n_b2,
    float* __restrict__ h_out)
{
    int node = blockIdx.x * 4 + (threadIdx.x >> 5);
    int f    = threadIdx.x & 31;
    float hv = h[node*FF + f];
    float mv = g_mi[node*FF + f];
    float acc = n_b1[f];
#pragma unroll
    for (int k = 0; k < FF; k++)
        acc += __shfl_sync(0xffffffffu, hv, k) * n_w1[k*HH + f];
#pragma unroll
    for (int k = 0; k < FF; k++)
        acc += __shfl_sync(0xffffffffu, mv, k) * n_w1[(FF + k)*HH + f];
    float tt = siluf(acc);
    float acc2 = n_b2[f];
#pragma unroll
    for (int k = 0; k < HH; k++)
        acc2 += __shfl_sync(0xffffffffu, tt, k) * n_w2[k*FF + f];
    h_out[node*FF + f] = hv + acc2;
}

// ---------------------------------------------------------------------------
extern "C" void kernel_launch(void* const* d_in, const int* in_sizes, int n_in,
                              void* d_out, int out_size)
{
    const float* x        = (const float*)d_in[0];
    const float* h        = (const float*)d_in[1];
    const float* d_static = (const float*)d_in[2];
    const float* e_w1     = (const float*)d_in[3];
    const float* e_b1     = (const float*)d_in[4];
    const float* e_w2     = (const float*)d_in[5];
    const float* e_b2     = (const float*)d_in[6];
    const float* n_w1     = (const float*)d_in[7];
    const float* n_b1     = (const float*)d_in[8];
    const float* n_w2     = (const float*)d_in[9];
    const float* n_b2     = (const float*)d_in[10];
    const float* c_w1     = (const float*)d_in[11];
    const float* c_b1     = (const float*)d_in[12];
    const float* c_w2     = (const float*)d_in[13];
    const float* a_w      = (const float*)d_in[14];
    const float* a_b      = (const float*)d_in[15];

    float* out   = (float*)d_out;
    float* x_out = out;                 // B*DIM floats
    float* h_out = out + BB*DIM;        // B*NP*FF floats

    prenode_kernel<<<NNODE/4, 128>>>(h, e_w1, e_b1);
    edge_kernel<<<BB*NP, 128>>>(x, d_static, e_w1, e_w2, e_b2,
                                c_w1, c_b1, c_w2, a_w, a_b, x_out);
    node_kernel<<<NNODE/4, 128>>>(h, n_w1, n_b1, n_w2, n_b2, h_out);
}

// round 3
// speedup vs baseline: 2.3758x; 1.1137x over previous
#include <cuda_runtime.h>
#include <math.h>

#define NP 128
#define ND 3
#define DIM (NP*ND)
#define FF 32
#define HH 32
#define BB 128
#define NEDGE (NP*(NP-1))   // 16256
#define NNODE (BB*NP)       // 16384

// scratch (static device arrays, no allocation)
__device__ float g_A [NNODE*FF];   // h_i @ W_hi + e_b1
__device__ float g_Bm[NNODE*FF];   // h_j @ W_hj

// ---- packed f32x2 helpers (FFMA2: only reachable via PTX on sm_103a) ----
#define FMA2(d,a,b,c) asm("fma.rn.f32x2 %0, %1, %2, %3;" : "=l"(d) : "l"(a), "l"(b), "l"(c))
#define ADD2(d,a,b)   asm("add.rn.f32x2 %0, %1, %2;"     : "=l"(d) : "l"(a), "l"(b))
#define PACK2(d,lo,hi) asm("mov.b64 %0, {%1, %2};" : "=l"(d) : "f"(lo), "f"(hi))
#define UNPK2(lo,hi,s) asm("mov.b64 {%0, %1}, %2;" : "=f"(lo), "=f"(hi) : "l"(s))

typedef unsigned long long u64;

union F4U2 { float4 f4; ulonglong2 u2; };

__device__ __forceinline__ float sigf(float v) {
    return __fdividef(1.0f, 1.0f + __expf(-v));
}
__device__ __forceinline__ float siluf(float v) {
    return __fdividef(v, 1.0f + __expf(-v));
}

// ---------------------------------------------------------------------------
// Kernel 0: per-node precompute A = h@W_hi + e_b1, Bm = h@W_hj
// ---------------------------------------------------------------------------
__global__ __launch_bounds__(128) void prenode_kernel(
    const float* __restrict__ h, const float* __restrict__ e_w1,
    const float* __restrict__ e_b1)
{
    int node = blockIdx.x * 4 + (threadIdx.x >> 5);
    int f    = threadIdx.x & 31;
    float hv = h[node*FF + f];
    float a  = e_b1[f];
    float bm = 0.0f;
#pragma unroll
    for (int k = 0; k < FF; k++) {
        float hk = __shfl_sync(0xffffffffu, hv, k);
        a  += hk * e_w1[k*HH + f];          // rows 0..31  : hi part
        bm += hk * e_w1[(FF + k)*HH + f];   // rows 32..63 : hj part
    }
    g_A [node*FF + f] = a;
    g_Bm[node*FF + f] = bm;
}

// ---------------------------------------------------------------------------
// Kernel 1: fused edge + node kernel.
// Block = (b, i). Thread j = 0..127 handles edge (i->j).
// Layer1 streams into layer2 accumulators (no s1 array); Bm staged through
// smem with coalesced loads; m reduced via lane-butterfly; node-update MLP
// fused into the warp-0 tail.
// ---------------------------------------------------------------------------
__global__ __launch_bounds__(128, 5) void edge_kernel(
    const float* __restrict__ x,      const float* __restrict__ d_static,
    const float* __restrict__ e_w1,   const float* __restrict__ e_w2,
    const float* __restrict__ e_b2,   const float* __restrict__ c_w1,
    const float* __restrict__ c_b1,   const float* __restrict__ c_w2,
    const float* __restrict__ a_w,    const float* __restrict__ a_b,
    const float* __restrict__ h,
    const float* __restrict__ n_w1,   const float* __restrict__ n_b1,
    const float* __restrict__ n_w2,   const float* __restrict__ n_b2,
    float* __restrict__ x_out,        float* __restrict__ h_out)
{
    __shared__ __align__(16) float s_w2[FF*HH];     // e_w2 (32x32)
    __shared__ __align__(16) float s_c1[FF*HH];     // c_w1 (32x32)
    __shared__ __align__(16) float s_misc[7*32];    // wd,wds,eb2,cb1,aw,cw2,Ai
    __shared__ __align__(16) float s_bm[NP*36];     // staged Bm rows, padded
    __shared__ float s_part[4][32];
    __shared__ float s_xp[4][3];
    __shared__ float s_xi[3];
    __shared__ float s_ab;

    const int t = threadIdx.x;
    const int bi = blockIdx.x;
    const int b = bi >> 7;
    const int i = bi & 127;
    const int j = t;
    const int lane = t & 31;
    const int warp = t >> 5;

    for (int idx = t; idx < FF*HH; idx += 128) {
        s_w2[idx] = e_w2[idx];
        s_c1[idx] = c_w1[idx];
    }
    // coalesced stage of Bm block row-set (128 rows x 32 floats) into smem
    {
        const float4* src = (const float4*)(g_Bm + b*NP*FF);
#pragma unroll
        for (int q = 0; q < 8; q++) {
            int idx = q*128 + t;           // float4 index
            int row = idx >> 3;
            int col = (idx & 7) * 4;
            *(float4*)(s_bm + row*36 + col) = src[idx];
        }
    }
    if (t < 32) {
        s_misc[t        ] = e_w1[(2*FF    )*HH + t];  // w_d
        s_misc[32  + t  ] = e_w1[(2*FF + 1)*HH + t];  // w_ds
        s_misc[64  + t  ] = e_b2[t];
        s_misc[96  + t  ] = c_b1[t];
        s_misc[128 + t  ] = a_w[t];
        s_misc[160 + t  ] = c_w2[t];
        s_misc[192 + t  ] = g_A[(b*NP + i)*FF + t];
    }
    if (t == 0) s_ab = a_b[0];
    if (t < 3)  s_xi[t] = x[b*DIM + i*ND + t];
    __syncthreads();

    // ---- edge geometry ----
    float xjx = x[b*DIM + j*ND + 0];
    float xjy = x[b*DIM + j*ND + 1];
    float xjz = x[b*DIM + j*ND + 2];
    float rx = s_xi[0] - xjx;
    float ry = s_xi[1] - xjy;
    float rz = s_xi[2] - xjz;
    float d2 = rx*rx + ry*ry + rz*rz;
    float d  = sqrtf(d2 + 1e-6f);

    int e = i*(NP-1) + (j < i ? j : j-1);
    if (j == i) e = 0;
    float ds  = d_static[b*NEDGE + e];
    float ds2 = ds*ds;

    // own Bm row -> packed pairs in registers
    u64 bmp[16];
    {
#pragma unroll
        for (int q = 0; q < 8; q++) {
            F4U2 v;
            v.f4 = *(const float4*)(s_bm + j*36 + q*4);
            bmp[2*q]   = v.u2.x;
            bmp[2*q+1] = v.u2.y;
        }
    }

    // ---- fused layer1 -> layer2: m2 += silu(pre_k) * w2[k,:] ----
    u64 m2[16];
    {
        const ulonglong2* b2 = (const ulonglong2*)(s_misc + 64);
#pragma unroll
        for (int q = 0; q < 8; q++) { ulonglong2 v = b2[q]; m2[2*q] = v.x; m2[2*q+1] = v.y; }
    }
    {
        u64 d2p, dsp;
        PACK2(d2p, d2, d2);
        PACK2(dsp, ds2, ds2);
        const u64* Ai  = (const u64*)(s_misc + 192);
        const u64* Wd  = (const u64*)(s_misc + 0);
        const u64* Wds = (const u64*)(s_misc + 32);
#pragma unroll
        for (int kp = 0; kp < 16; kp++) {
            u64 pre;
            ADD2(pre, Ai[kp], bmp[kp]);
            FMA2(pre, d2p, Wd[kp], pre);
            FMA2(pre, dsp, Wds[kp], pre);
            float v0, v1;
            UNPK2(v0, v1, pre);
            v0 = siluf(v0);
            v1 = siluf(v1);
            u64 s0, s1p;
            PACK2(s0,  v0, v0);
            PACK2(s1p, v1, v1);
            const ulonglong2* w0 = (const ulonglong2*)(s_w2 + (2*kp)*HH);
#pragma unroll
            for (int q = 0; q < 8; q++) {
                ulonglong2 wa = w0[q], wb = w0[q+8];   // rows 2kp, 2kp+1
                FMA2(m2[2*q],   s0,  wa.x, m2[2*q]);
                FMA2(m2[2*q+1], s0,  wa.y, m2[2*q+1]);
                FMA2(m2[2*q],   s1p, wb.x, m2[2*q]);
                FMA2(m2[2*q+1], s1p, wb.y, m2[2*q+1]);
            }
        }
    }

    // ---- silu + attention gate ----
    float m[FF];
#pragma unroll
    for (int q = 0; q < 16; q++) UNPK2(m[2*q], m[2*q+1], m2[q]);
#pragma unroll
    for (int f = 0; f < FF; f++) m[f] = siluf(m[f]);

    float att = s_ab;
#pragma unroll
    for (int f = 0; f < FF; f++) att += m[f] * s_misc[128 + f];
    att = sigf(att);
#pragma unroll
    for (int f = 0; f < FF; f++) m[f] *= att;

    // ---- coord head: trans = tanh(silu(m @ c_w1 + c_b1) @ c_w2) ----
    float trans;
    {
        u64 c2[16];
        const ulonglong2* b2 = (const ulonglong2*)(s_misc + 96);
#pragma unroll
        for (int q = 0; q < 8; q++) { ulonglong2 v = b2[q]; c2[2*q] = v.x; c2[2*q+1] = v.y; }
#pragma unroll
        for (int f = 0; f < FF; f++) {
            u64 mp; PACK2(mp, m[f], m[f]);
            const ulonglong2* wr = (const ulonglong2*)(s_c1 + f*HH);
#pragma unroll
            for (int q = 0; q < 8; q++) {
                ulonglong2 wv = wr[q];
                FMA2(c2[2*q],   mp, wv.x, c2[2*q]);
                FMA2(c2[2*q+1], mp, wv.y, c2[2*q+1]);
            }
        }
        float acc = 0.0f;
#pragma unroll
        for (int q = 0; q < 16; q++) {
            float c0, c1v;
            UNPK2(c0, c1v, c2[q]);
            acc += siluf(c0)  * s_misc[160 + 2*q];
            acc += siluf(c1v) * s_misc[160 + 2*q + 1];
        }
        trans = tanhf(acc);
    }

    float valid = (j == i) ? 0.0f : 1.0f;
    float coef = valid * __fdividef(trans, d + 1.0f);
#pragma unroll
    for (int f = 0; f < FF; f++) m[f] *= valid;

    // ---- reduce coord update across the 128 threads (warp bfly + smem) ----
    float xc0 = rx*coef, xc1 = ry*coef, xc2 = rz*coef;
#pragma unroll
    for (int off = 16; off > 0; off >>= 1) {
        xc0 += __shfl_xor_sync(0xffffffffu, xc0, off);
        xc1 += __shfl_xor_sync(0xffffffffu, xc1, off);
        xc2 += __shfl_xor_sync(0xffffffffu, xc2, off);
    }
    if (lane == 0) { s_xp[warp][0] = xc0; s_xp[warp][1] = xc1; s_xp[warp][2] = xc2; }

    // ---- butterfly vector reduce of m across lanes:
    //      after 5 steps lane f holds sum over this warp's lanes of m[f] ----
#pragma unroll
    for (int off = 16, nh = 16; off > 0; off >>= 1, nh >>= 1) {
        bool hi = (lane & off);
#pragma unroll
        for (int tt = 0; tt < 16; tt++) {
            if (tt < nh) {
                float kept = hi ? m[nh + tt] : m[tt];
                float sent = hi ? m[tt]      : m[nh + tt];
                float recv = __shfl_xor_sync(0xffffffffu, sent, off);
                m[tt] = kept + recv;
            }
        }
    }
    s_part[warp][lane] = m[0];
    __syncthreads();

    // ---- warp-0 tail: finish mi, node-update MLP, write outputs ----
    if (t < 3) {
        float xs = s_xp[0][t] + s_xp[1][t] + s_xp[2][t] + s_xp[3][t];
        x_out[b*DIM + i*ND + t] = s_xi[t] + xs * 5.0f;   // COORDS_RANGE
    }
    if (warp == 0) {
        int f = lane;
        float mi = s_part[0][f] + s_part[1][f] + s_part[2][f] + s_part[3][f];
        float hv = h[(b*NP + i)*FF + f];
        float acc = n_b1[f];
#pragma unroll
        for (int k = 0; k < FF; k++)
            acc += __shfl_sync(0xffffffffu, hv, k) * n_w1[k*HH + f];
#pragma unroll
        for (int k = 0; k < FF; k++)
            acc += __shfl_sync(0xffffffffu, mi, k) * n_w1[(FF + k)*HH + f];
        float tt2 = siluf(acc);
        float acc2 = n_b2[f];
#pragma unroll
        for (int k = 0; k < HH; k++)
            acc2 += __shfl_sync(0xffffffffu, tt2, k) * n_w2[k*FF + f];
        h_out[(b*NP + i)*FF + f] = hv + acc2;
    }
}

// ---------------------------------------------------------------------------
extern "C" void kernel_launch(void* const* d_in, const int* in_sizes, int n_in,
                              void* d_out, int out_size)
{
    const float* x        = (const float*)d_in[0];
    const float* h        = (const float*)d_in[1];
    const float* d_static = (const float*)d_in[2];
    const float* e_w1     = (const float*)d_in[3];
    const float* e_b1     = (const float*)d_in[4];
    const float* e_w2     = (const float*)d_in[5];
    const float* e_b2     = (const float*)d_in[6];
    const float* n_w1     = (const float*)d_in[7];
    const float* n_b1     = (const float*)d_in[8];
    const float* n_w2     = (const float*)d_in[9];
    const float* n_b2     = (const float*)d_in[10];
    const float* c_w1     = (const float*)d_in[11];
    const float* c_b1     = (const float*)d_in[12];
    const float* c_w2     = (const float*)d_in[13];
    const float* a_w      = (const float*)d_in[14];
    const float* a_b      = (const float*)d_in[15];

    float* out   = (float*)d_out;
    float* x_out = out;                 // B*DIM floats
    float* h_out = out + BB*DIM;        // B*NP*FF floats

    prenode_kernel<<<NNODE/4, 128>>>(h, e_w1, e_b1);
    edge_kernel<<<BB*NP, 128>>>(x, d_static, e_w1, e_w2, e_b2,
                                c_w1, c_b1, c_w2, a_w, a_b,
                                h, n_w1, n_b1, n_w2, n_b2,
                                x_out, h_out);
}

// round 4
// speedup vs baseline: 2.5318x; 1.0657x over previous
#include <cuda_runtime.h>
#include <math.h>

#define NP 128
#define ND 3
#define DIM (NP*ND)
#define FF 32
#define HH 32
#define BB 128
#define NEDGE (NP*(NP-1))   // 16256
#define NNODE (BB*NP)       // 16384
#define SBM 34              // padded Bm row stride (2-way conflict on u64, tolerable)

// scratch (static device arrays, no allocation)
__device__ float g_A [NNODE*FF];   // h_i @ W_hi + e_b1
__device__ float g_Bm[NNODE*FF];   // h_j @ W_hj

// ---- packed f32x2 helpers (FFMA2: only reachable via PTX on sm_103a) ----
#define FMA2(d,a,b,c) asm("fma.rn.f32x2 %0, %1, %2, %3;" : "=l"(d) : "l"(a), "l"(b), "l"(c))
#define ADD2(d,a,b)   asm("add.rn.f32x2 %0, %1, %2;"     : "=l"(d) : "l"(a), "l"(b))
#define MUL2(d,a,b)   asm("mul.rn.f32x2 %0, %1, %2;"     : "=l"(d) : "l"(a), "l"(b))
#define PACK2(d,lo,hi) asm("mov.b64 %0, {%1, %2};" : "=l"(d) : "f"(lo), "f"(hi))
#define UNPK2(lo,hi,s) asm("mov.b64 {%0, %1}, %2;" : "=f"(lo), "=f"(hi) : "l"(s))

typedef unsigned long long u64;

__device__ __forceinline__ float sigf(float v) {
    return __fdividef(1.0f, 1.0f + __expf(-v));
}
__device__ __forceinline__ float siluf(float v) {
    return __fdividef(v, 1.0f + __expf(-v));
}

// ---------------------------------------------------------------------------
// Kernel 0: per-node precompute A = h@W_hi + e_b1, Bm = h@W_hj
// ---------------------------------------------------------------------------
__global__ __launch_bounds__(128) void prenode_kernel(
    const float* __restrict__ h, const float* __restrict__ e_w1,
    const float* __restrict__ e_b1)
{
    int node = blockIdx.x * 4 + (threadIdx.x >> 5);
    int f    = threadIdx.x & 31;
    float hv = h[node*FF + f];
    float a  = e_b1[f];
    float bm = 0.0f;
#pragma unroll
    for (int k = 0; k < FF; k++) {
        float hk = __shfl_sync(0xffffffffu, hv, k);
        a  += hk * e_w1[k*HH + f];
        bm += hk * e_w1[(FF + k)*HH + f];
    }
    g_A [node*FF + f] = a;
    g_Bm[node*FF + f] = bm;
}

// ---------------------------------------------------------------------------
// Kernel 1: fused edge + node kernel, TWO i's per block.
// Block = (b, i0=2*ip, i1=2*ip+1). Thread j handles edges (i0->j) AND (i1->j):
// every weight LDS (layer2 + coord head, interleaved) is shared by both edges.
// ---------------------------------------------------------------------------
__global__ __launch_bounds__(128, 3) void edge_kernel(
    const float* __restrict__ x,      const float* __restrict__ d_static,
    const float* __restrict__ e_w1,   const float* __restrict__ e_w2,
    const float* __restrict__ e_b2,   const float* __restrict__ c_w1,
    const float* __restrict__ c_b1,   const float* __restrict__ c_w2,
    const float* __restrict__ a_w,    const float* __restrict__ a_b,
    const float* __restrict__ h,
    const float* __restrict__ n_w1,   const float* __restrict__ n_b1,
    const float* __restrict__ n_w2,   const float* __restrict__ n_b2,
    float* __restrict__ x_out,        float* __restrict__ h_out)
{
    __shared__ __align__(16) float s_w2[FF*HH];     // e_w2
    __shared__ __align__(16) float s_c1[FF*HH];     // c_w1
    __shared__ __align__(16) float s_misc[8*32];    // wd,wds,eb2,cb1,aw,cw2,Ai0,Ai1
    __shared__ __align__(16) float s_bm[NP*SBM];    // staged Bm rows (whole batch b)
    __shared__ float s_part[2][4][32];
    __shared__ float s_xp[2][4][3];
    __shared__ float s_xi[2][3];
    __shared__ float s_ab;

    const int t = threadIdx.x;
    const int b  = blockIdx.x >> 6;
    const int ip = blockIdx.x & 63;
    const int i0 = ip*2, i1 = i0+1;
    const int j = t;
    const int lane = t & 31;
    const int warp = t >> 5;

    for (int idx = t; idx < FF*HH; idx += 128) {
        s_w2[idx] = e_w2[idx];
        s_c1[idx] = c_w1[idx];
    }
    {   // coalesced stage of Bm for batch b (128 rows x 32 floats), stride SBM
        const float4* src = (const float4*)(g_Bm + b*NP*FF);
#pragma unroll
        for (int q = 0; q < 8; q++) {
            int idx = q*128 + t;
            int row = idx >> 3;
            int col = (idx & 7) * 4;
            float4 v = src[idx];
            s_bm[row*SBM + col + 0] = v.x;
            s_bm[row*SBM + col + 1] = v.y;
            s_bm[row*SBM + col + 2] = v.z;
            s_bm[row*SBM + col + 3] = v.w;
        }
    }
    if (t < 32) {
        s_misc[t        ] = e_w1[(2*FF    )*HH + t];  // w_d
        s_misc[32  + t  ] = e_w1[(2*FF + 1)*HH + t];  // w_ds
        s_misc[64  + t  ] = e_b2[t];
        s_misc[96  + t  ] = c_b1[t];
        s_misc[128 + t  ] = a_w[t];
        s_misc[160 + t  ] = c_w2[t];
        s_misc[192 + t  ] = g_A[(b*NP + i0)*FF + t];
        s_misc[224 + t  ] = g_A[(b*NP + i1)*FF + t];
    }
    if (t == 0) s_ab = a_b[0];
    if (t < 6)  s_xi[t/3][t%3] = x[b*DIM + (t < 3 ? i0 : i1)*ND + (t%3)];
    __syncthreads();

    // ---- geometry for both edges (shared x_j load) ----
    float xj0 = x[b*DIM + j*ND + 0];
    float xj1 = x[b*DIM + j*ND + 1];
    float xj2 = x[b*DIM + j*ND + 2];
    float rxa = s_xi[0][0]-xj0, rya = s_xi[0][1]-xj1, rza = s_xi[0][2]-xj2;
    float rxb = s_xi[1][0]-xj0, ryb = s_xi[1][1]-xj1, rzb = s_xi[1][2]-xj2;
    float d2a = rxa*rxa + rya*rya + rza*rza;
    float d2b = rxb*rxb + ryb*ryb + rzb*rzb;
    float da = sqrtf(d2a + 1e-6f);
    float db = sqrtf(d2b + 1e-6f);

    int ea = i0*(NP-1) + (j < i0 ? j : j-1); if (j == i0) ea = 0;
    int eb = i1*(NP-1) + (j < i1 ? j : j-1); if (j == i1) eb = 0;
    float dsa = d_static[b*NEDGE + ea];
    float dsb = d_static[b*NEDGE + eb];
    float ds2a = dsa*dsa, ds2b = dsb*dsb;

    u64 d2ap, ds2ap, d2bp, ds2bp;
    PACK2(d2ap, d2a, d2a);  PACK2(ds2ap, ds2a, ds2a);
    PACK2(d2bp, d2b, d2b);  PACK2(ds2bp, ds2b, ds2b);

    // ---- fused layer1->layer2 for both edges, weights loaded once ----
    u64 m2a[16], m2b[16];
    {
        const ulonglong2* bp = (const ulonglong2*)(s_misc + 64);
#pragma unroll
        for (int q = 0; q < 8; q++) {
            ulonglong2 v = bp[q];
            m2a[2*q] = v.x;  m2a[2*q+1] = v.y;
            m2b[2*q] = v.x;  m2b[2*q+1] = v.y;
        }
    }
    {
        const u64* Ai0p = (const u64*)(s_misc + 192);
        const u64* Ai1p = (const u64*)(s_misc + 224);
        const u64* Wd   = (const u64*)(s_misc + 0);
        const u64* Wds  = (const u64*)(s_misc + 32);
#pragma unroll 4
        for (int kp = 0; kp < 16; kp++) {
            u64 bm = *(const u64*)(s_bm + j*SBM + 2*kp);
            u64 wd = Wd[kp], ws = Wds[kp];
            u64 pa, pb;
            ADD2(pa, Ai0p[kp], bm);
            FMA2(pa, d2ap, wd, pa);
            FMA2(pa, ds2ap, ws, pa);
            ADD2(pb, Ai1p[kp], bm);
            FMA2(pb, d2bp, wd, pb);
            FMA2(pb, ds2bp, ws, pb);
            float va0, va1, vb0, vb1;
            UNPK2(va0, va1, pa);
            UNPK2(vb0, vb1, pb);
            va0 = siluf(va0); va1 = siluf(va1);
            vb0 = siluf(vb0); vb1 = siluf(vb1);
            u64 s0a, s1a, s0b, s1b;
            PACK2(s0a, va0, va0); PACK2(s1a, va1, va1);
            PACK2(s0b, vb0, vb0); PACK2(s1b, vb1, vb1);
            const ulonglong2* w0 = (const ulonglong2*)(s_w2 + (2*kp)*HH);
#pragma unroll
            for (int q = 0; q < 8; q++) {
                ulonglong2 wa = w0[q], wb = w0[q+8];
                FMA2(m2a[2*q],   s0a, wa.x, m2a[2*q]);
                FMA2(m2a[2*q+1], s0a, wa.y, m2a[2*q+1]);
                FMA2(m2a[2*q],   s1a, wb.x, m2a[2*q]);
                FMA2(m2a[2*q+1], s1a, wb.y, m2a[2*q+1]);
                FMA2(m2b[2*q],   s0b, wa.x, m2b[2*q]);
                FMA2(m2b[2*q+1], s0b, wa.y, m2b[2*q+1]);
                FMA2(m2b[2*q],   s1b, wb.x, m2b[2*q]);
                FMA2(m2b[2*q+1], s1b, wb.y, m2b[2*q+1]);
            }
        }
    }

    // ---- silu on m (kept packed) ----
#pragma unroll
    for (int q = 0; q < 16; q++) {
        float v0, v1;
        UNPK2(v0, v1, m2a[q]); v0 = siluf(v0); v1 = siluf(v1); PACK2(m2a[q], v0, v1);
        UNPK2(v0, v1, m2b[q]); v0 = siluf(v0); v1 = siluf(v1); PACK2(m2b[q], v0, v1);
    }

    // ---- attention gates (packed dot) ----
    {
        const u64* awp = (const u64*)(s_misc + 128);
        u64 ata = 0ull, atb = 0ull;
#pragma unroll
        for (int q = 0; q < 16; q++) {
            u64 w = awp[q];
            FMA2(ata, m2a[q], w, ata);
            FMA2(atb, m2b[q], w, atb);
        }
        float a0, a1;
        UNPK2(a0, a1, ata);
        float atta = sigf(a0 + a1 + s_ab);
        UNPK2(a0, a1, atb);
        float attb = sigf(a0 + a1 + s_ab);
        u64 pa, pb;
        PACK2(pa, atta, atta);
        PACK2(pb, attb, attb);
#pragma unroll
        for (int q = 0; q < 16; q++) {
            MUL2(m2a[q], m2a[q], pa);
            MUL2(m2b[q], m2b[q], pb);
        }
    }

    // ---- coord head, interleaved: weights loaded once for both edges ----
    float transa, transb;
    {
        u64 c2a[16], c2b[16];
        const ulonglong2* cb = (const ulonglong2*)(s_misc + 96);
#pragma unroll
        for (int q = 0; q < 8; q++) {
            ulonglong2 v = cb[q];
            c2a[2*q] = v.x;  c2a[2*q+1] = v.y;
            c2b[2*q] = v.x;  c2b[2*q+1] = v.y;
        }
#pragma unroll 4
        for (int fp = 0; fp < 16; fp++) {
            float ma0, ma1, mb0, mb1;
            UNPK2(ma0, ma1, m2a[fp]);
            UNPK2(mb0, mb1, m2b[fp]);
            u64 pa0, pa1, pb0, pb1;
            PACK2(pa0, ma0, ma0); PACK2(pa1, ma1, ma1);
            PACK2(pb0, mb0, mb0); PACK2(pb1, mb1, mb1);
            const ulonglong2* wr = (const ulonglong2*)(s_c1 + (2*fp)*HH);
#pragma unroll
            for (int q = 0; q < 8; q++) {
                ulonglong2 wa = wr[q], wb = wr[q+8];
                FMA2(c2a[2*q],   pa0, wa.x, c2a[2*q]);
                FMA2(c2a[2*q+1], pa0, wa.y, c2a[2*q+1]);
                FMA2(c2a[2*q],   pa1, wb.x, c2a[2*q]);
                FMA2(c2a[2*q+1], pa1, wb.y, c2a[2*q+1]);
                FMA2(c2b[2*q],   pb0, wa.x, c2b[2*q]);
                FMA2(c2b[2*q+1], pb0, wa.y, c2b[2*q+1]);
                FMA2(c2b[2*q],   pb1, wb.x, c2b[2*q]);
                FMA2(c2b[2*q+1], pb1, wb.y, c2b[2*q+1]);
            }
        }
        float acca = 0.0f, accb = 0.0f;
#pragma unroll
        for (int q = 0; q < 16; q++) {
            float c0, c1v;
            UNPK2(c0, c1v, c2a[q]);
            acca += siluf(c0)  * s_misc[160 + 2*q];
            acca += siluf(c1v) * s_misc[160 + 2*q + 1];
            UNPK2(c0, c1v, c2b[q]);
            accb += siluf(c0)  * s_misc[160 + 2*q];
            accb += siluf(c1v) * s_misc[160 + 2*q + 1];
        }
        transa = tanhf(acca);
        transb = tanhf(accb);
    }

    float valida = (j == i0) ? 0.0f : 1.0f;
    float validb = (j == i1) ? 0.0f : 1.0f;
    float coefa = valida * __fdividef(transa, da + 1.0f);
    float coefb = validb * __fdividef(transb, db + 1.0f);

    // ---- coord reductions (both edges) ----
    {
        float x0 = rxa*coefa, x1 = rya*coefa, x2 = rza*coefa;
        float y0 = rxb*coefb, y1 = ryb*coefb, y2 = rzb*coefb;
#pragma unroll
        for (int off = 16; off > 0; off >>= 1) {
            x0 += __shfl_xor_sync(0xffffffffu, x0, off);
            x1 += __shfl_xor_sync(0xffffffffu, x1, off);
            x2 += __shfl_xor_sync(0xffffffffu, x2, off);
            y0 += __shfl_xor_sync(0xffffffffu, y0, off);
            y1 += __shfl_xor_sync(0xffffffffu, y1, off);
            y2 += __shfl_xor_sync(0xffffffffu, y2, off);
        }
        if (lane == 0) {
            s_xp[0][warp][0] = x0; s_xp[0][warp][1] = x1; s_xp[0][warp][2] = x2;
            s_xp[1][warp][0] = y0; s_xp[1][warp][1] = y1; s_xp[1][warp][2] = y2;
        }
    }

    // ---- butterfly vector reduce of m over lanes, edge a then edge b ----
    {
        float mm[FF];
#pragma unroll
        for (int q = 0; q < 16; q++) UNPK2(mm[2*q], mm[2*q+1], m2a[q]);
#pragma unroll
        for (int f = 0; f < FF; f++) mm[f] *= valida;
#pragma unroll
        for (int off = 16, nh = 16; off > 0; off >>= 1, nh >>= 1) {
            bool hi = (lane & off);
#pragma unroll
            for (int tt = 0; tt < 16; tt++) {
                if (tt < nh) {
                    float kept = hi ? mm[nh + tt] : mm[tt];
                    float sent = hi ? mm[tt]      : mm[nh + tt];
                    float recv = __shfl_xor_sync(0xffffffffu, sent, off);
                    mm[tt] = kept + recv;
                }
            }
        }
        s_part[0][warp][lane] = mm[0];
#pragma unroll
        for (int q = 0; q < 16; q++) UNPK2(mm[2*q], mm[2*q+1], m2b[q]);
#pragma unroll
        for (int f = 0; f < FF; f++) mm[f] *= validb;
#pragma unroll
        for (int off = 16, nh = 16; off > 0; off >>= 1, nh >>= 1) {
            bool hi = (lane & off);
#pragma unroll
            for (int tt = 0; tt < 16; tt++) {
                if (tt < nh) {
                    float kept = hi ? mm[nh + tt] : mm[tt];
                    float sent = hi ? mm[tt]      : mm[nh + tt];
                    float recv = __shfl_xor_sync(0xffffffffu, sent, off);
                    mm[tt] = kept + recv;
                }
            }
        }
        s_part[1][warp][lane] = mm[0];
    }
    __syncthreads();

    // ---- tail: warp 0 -> node i0, warp 1 -> node i1 ----
    if (warp < 2) {
        int e = warp;
        int node = b*NP + i0 + e;
        int f = lane;
        if (f < 3) {
            float xs = s_xp[e][0][f] + s_xp[e][1][f] + s_xp[e][2][f] + s_xp[e][3][f];
            x_out[b*DIM + (i0+e)*ND + f] = s_xi[e][f] + xs * 5.0f;   // COORDS_RANGE
        }
        float mi = s_part[e][0][f] + s_part[e][1][f] + s_part[e][2][f] + s_part[e][3][f];
        float hv = h[node*FF + f];
        float acc = n_b1[f];
#pragma unroll
        for (int k = 0; k < FF; k++)
            acc += __shfl_sync(0xffffffffu, hv, k) * n_w1[k*HH + f];
#pragma unroll
        for (int k = 0; k < FF; k++)
            acc += __shfl_sync(0xffffffffu, mi, k) * n_w1[(FF + k)*HH + f];
        float tt2 = siluf(acc);
        float acc2 = n_b2[f];
#pragma unroll
        for (int k = 0; k < HH; k++)
            acc2 += __shfl_sync(0xffffffffu, tt2, k) * n_w2[k*FF + f];
        h_out[node*FF + f] = hv + acc2;
    }
}

// ---------------------------------------------------------------------------
extern "C" void kernel_launch(void* const* d_in, const int* in_sizes, int n_in,
                              void* d_out, int out_size)
{
    const float* x        = (const float*)d_in[0];
    const float* h        = (const float*)d_in[1];
    const float* d_static = (const float*)d_in[2];
    const float* e_w1     = (const float*)d_in[3];
    const float* e_b1     = (const float*)d_in[4];
    const float* e_w2     = (const float*)d_in[5];
    const float* e_b2     = (const float*)d_in[6];
    const float* n_w1     = (const float*)d_in[7];
    const float* n_b1     = (const float*)d_in[8];
    const float* n_w2     = (const float*)d_in[9];
    const float* n_b2     = (const float*)d_in[10];
    const float* c_w1     = (const float*)d_in[11];
    const float* c_b1     = (const float*)d_in[12];
    const float* c_w2     = (const float*)d_in[13];
    const float* a_w      = (const float*)d_in[14];
    const float* a_b      = (const float*)d_in[15];

    float* out   = (float*)d_out;
    float* x_out = out;                 // B*DIM floats
    float* h_out = out + BB*DIM;        // B*NP*FF floats

    prenode_kernel<<<NNODE/4, 128>>>(h, e_w1, e_b1);
    edge_kernel<<<BB*NP/2, 128>>>(x, d_static, e_w1, e_w2, e_b2,
                                  c_w1, c_b1, c_w2, a_w, a_b,
                                  h, n_w1, n_b1, n_w2, n_b2,
                                  x_out, h_out);
}

// round 5
// speedup vs baseline: 2.5513x; 1.0077x over previous
#include <cuda_runtime.h>
#include <math.h>

#define NP 128
#define ND 3
#define DIM (NP*ND)
#define FF 32
#define HH 32
#define BB 128
#define NEDGE (NP*(NP-1))   // 16256
#define NNODE (BB*NP)       // 16384
#define SBM 34              // padded Bm row stride (2-way conflict on u64, tolerable)

// scratch (static device arrays, no allocation)
__device__ float g_A [NNODE*FF];   // h_i @ W_hi + e_b1
__device__ float g_Bm[NNODE*FF];   // h_j @ W_hj

// ---- packed f32x2 helpers (FFMA2: only reachable via PTX on sm_103a) ----
#define FMA2(d,a,b,c) asm("fma.rn.f32x2 %0, %1, %2, %3;" : "=l"(d) : "l"(a), "l"(b), "l"(c))
#define ADD2(d,a,b)   asm("add.rn.f32x2 %0, %1, %2;"     : "=l"(d) : "l"(a), "l"(b))
#define MUL2(d,a,b)   asm("mul.rn.f32x2 %0, %1, %2;"     : "=l"(d) : "l"(a), "l"(b))
#define PACK2(d,lo,hi) asm("mov.b64 %0, {%1, %2};" : "=l"(d) : "f"(lo), "f"(hi))
#define UNPK2(lo,hi,s) asm("mov.b64 {%0, %1}, %2;" : "=f"(lo), "=f"(hi) : "l"(s))

typedef unsigned long long u64;

__device__ __forceinline__ float sigf(float v) {
    return __fdividef(1.0f, 1.0f + __expf(-v));
}
__device__ __forceinline__ float siluf(float v) {
    return __fdividef(v, 1.0f + __expf(-v));
}

// ---------------------------------------------------------------------------
// Kernel 0: per-node precompute A = h@W_hi + e_b1, Bm = h@W_hj
// ---------------------------------------------------------------------------
__global__ __launch_bounds__(128) void prenode_kernel(
    const float* __restrict__ h, const float* __restrict__ e_w1,
    const float* __restrict__ e_b1)
{
    int node = blockIdx.x * 4 + (threadIdx.x >> 5);
    int f    = threadIdx.x & 31;
    float hv = h[node*FF + f];
    float a  = e_b1[f];
    float bm = 0.0f;
#pragma unroll
    for (int k = 0; k < FF; k++) {
        float hk = __shfl_sync(0xffffffffu, hv, k);
        a  += hk * e_w1[k*HH + f];
        bm += hk * e_w1[(FF + k)*HH + f];
    }
    g_A [node*FF + f] = a;
    g_Bm[node*FF + f] = bm;
}

// ---------------------------------------------------------------------------
// Kernel 1: fused edge + node kernel, TWO i's per block.
// Block = (b, i0=2*ip, i1=2*ip+1). Thread j handles edges (i0->j) AND (i1->j):
// every weight LDS (layer2 + coord head, interleaved) is shared by both edges.
// ---------------------------------------------------------------------------
__global__ __launch_bounds__(128, 3) void edge_kernel(
    const float* __restrict__ x,      const float* __restrict__ d_static,
    const float* __restrict__ e_w1,   const float* __restrict__ e_w2,
    const float* __restrict__ e_b2,   const float* __restrict__ c_w1,
    const float* __restrict__ c_b1,   const float* __restrict__ c_w2,
    const float* __restrict__ a_w,    const float* __restrict__ a_b,
    const float* __restrict__ h,
    const float* __restrict__ n_w1,   const float* __restrict__ n_b1,
    const float* __restrict__ n_w2,   const float* __restrict__ n_b2,
    float* __restrict__ x_out,        float* __restrict__ h_out)
{
    __shared__ __align__(16) float s_w2[FF*HH];     // e_w2
    __shared__ __align__(16) float s_c1[FF*HH];     // c_w1
    __shared__ __align__(16) float s_misc[8*32];    // wd,wds,eb2,cb1,aw,cw2,Ai0,Ai1
    __shared__ __align__(16) float s_bm[NP*SBM];    // staged Bm rows (whole batch b)
    __shared__ float s_part[2][4][32];
    __shared__ float s_xp[2][4][3];
    __shared__ float s_xi[2][3];
    __shared__ float s_ab;

    const int t = threadIdx.x;
    const int b  = blockIdx.x >> 6;
    const int ip = blockIdx.x & 63;
    const int i0 = ip*2, i1 = i0+1;
    const int j = t;
    const int lane = t & 31;
    const int warp = t >> 5;

    for (int idx = t; idx < FF*HH; idx += 128) {
        s_w2[idx] = e_w2[idx];
        s_c1[idx] = c_w1[idx];
    }
    {   // coalesced stage of Bm for batch b (128 rows x 32 floats), stride SBM
        const float4* src = (const float4*)(g_Bm + b*NP*FF);
#pragma unroll
        for (int q = 0; q < 8; q++) {
            int idx = q*128 + t;
            int row = idx >> 3;
            int col = (idx & 7) * 4;
            float4 v = src[idx];
            s_bm[row*SBM + col + 0] = v.x;
            s_bm[row*SBM + col + 1] = v.y;
            s_bm[row*SBM + col + 2] = v.z;
            s_bm[row*SBM + col + 3] = v.w;
        }
    }
    if (t < 32) {
        s_misc[t        ] = e_w1[(2*FF    )*HH + t];  // w_d
        s_misc[32  + t  ] = e_w1[(2*FF + 1)*HH + t];  // w_ds
        s_misc[64  + t  ] = e_b2[t];
        s_misc[96  + t  ] = c_b1[t];
        s_misc[128 + t  ] = a_w[t];
        s_misc[160 + t  ] = c_w2[t];
        s_misc[192 + t  ] = g_A[(b*NP + i0)*FF + t];
        s_misc[224 + t  ] = g_A[(b*NP + i1)*FF + t];
    }
    if (t == 0) s_ab = a_b[0];
    if (t < 6)  s_xi[t/3][t%3] = x[b*DIM + (t < 3 ? i0 : i1)*ND + (t%3)];
    __syncthreads();

    // ---- geometry for both edges (shared x_j load) ----
    float xj0 = x[b*DIM + j*ND + 0];
    float xj1 = x[b*DIM + j*ND + 1];
    float xj2 = x[b*DIM + j*ND + 2];
    float rxa = s_xi[0][0]-xj0, rya = s_xi[0][1]-xj1, rza = s_xi[0][2]-xj2;
    float rxb = s_xi[1][0]-xj0, ryb = s_xi[1][1]-xj1, rzb = s_xi[1][2]-xj2;
    float d2a = rxa*rxa + rya*rya + rza*rza;
    float d2b = rxb*rxb + ryb*ryb + rzb*rzb;
    float da = sqrtf(d2a + 1e-6f);
    float db = sqrtf(d2b + 1e-6f);

    int ea = i0*(NP-1) + (j < i0 ? j : j-1); if (j == i0) ea = 0;
    int eb = i1*(NP-1) + (j < i1 ? j : j-1); if (j == i1) eb = 0;
    float dsa = d_static[b*NEDGE + ea];
    float dsb = d_static[b*NEDGE + eb];
    float ds2a = dsa*dsa, ds2b = dsb*dsb;

    u64 d2ap, ds2ap, d2bp, ds2bp;
    PACK2(d2ap, d2a, d2a);  PACK2(ds2ap, ds2a, ds2a);
    PACK2(d2bp, d2b, d2b);  PACK2(ds2bp, ds2b, ds2b);

    // ---- fused layer1->layer2 for both edges, weights loaded once ----
    u64 m2a[16], m2b[16];
    {
        const ulonglong2* bp = (const ulonglong2*)(s_misc + 64);
#pragma unroll
        for (int q = 0; q < 8; q++) {
            ulonglong2 v = bp[q];
            m2a[2*q] = v.x;  m2a[2*q+1] = v.y;
            m2b[2*q] = v.x;  m2b[2*q+1] = v.y;
        }
    }
    {
        const u64* Ai0p = (const u64*)(s_misc + 192);
        const u64* Ai1p = (const u64*)(s_misc + 224);
        const u64* Wd   = (const u64*)(s_misc + 0);
        const u64* Wds  = (const u64*)(s_misc + 32);
#pragma unroll 4
        for (int kp = 0; kp < 16; kp++) {
            u64 bm = *(const u64*)(s_bm + j*SBM + 2*kp);
            u64 wd = Wd[kp], ws = Wds[kp];
            u64 pa, pb;
            ADD2(pa, Ai0p[kp], bm);
            FMA2(pa, d2ap, wd, pa);
            FMA2(pa, ds2ap, ws, pa);
            ADD2(pb, Ai1p[kp], bm);
            FMA2(pb, d2bp, wd, pb);
            FMA2(pb, ds2bp, ws, pb);
            float va0, va1, vb0, vb1;
            UNPK2(va0, va1, pa);
            UNPK2(vb0, vb1, pb);
            va0 = siluf(va0); va1 = siluf(va1);
            vb0 = siluf(vb0); vb1 = siluf(vb1);
            u64 s0a, s1a, s0b, s1b;
            PACK2(s0a, va0, va0); PACK2(s1a, va1, va1);
            PACK2(s0b, vb0, vb0); PACK2(s1b, vb1, vb1);
            const ulonglong2* w0 = (const ulonglong2*)(s_w2 + (2*kp)*HH);
#pragma unroll
            for (int q = 0; q < 8; q++) {
                ulonglong2 wa = w0[q], wb = w0[q+8];
                FMA2(m2a[2*q],   s0a, wa.x, m2a[2*q]);
                FMA2(m2a[2*q+1], s0a, wa.y, m2a[2*q+1]);
                FMA2(m2a[2*q],   s1a, wb.x, m2a[2*q]);
                FMA2(m2a[2*q+1], s1a, wb.y, m2a[2*q+1]);
                FMA2(m2b[2*q],   s0b, wa.x, m2b[2*q]);
                FMA2(m2b[2*q+1], s0b, wa.y, m2b[2*q+1]);
                FMA2(m2b[2*q],   s1b, wb.x, m2b[2*q]);
                FMA2(m2b[2*q+1], s1b, wb.y, m2b[2*q+1]);
            }
        }
    }

    // ---- silu on m (kept packed) ----
#pragma unroll
    for (int q = 0; q < 16; q++) {
        float v0, v1;
        UNPK2(v0, v1, m2a[q]); v0 = siluf(v0); v1 = siluf(v1); PACK2(m2a[q], v0, v1);
        UNPK2(v0, v1, m2b[q]); v0 = siluf(v0); v1 = siluf(v1); PACK2(m2b[q], v0, v1);
    }

    // ---- attention gates (packed dot) ----
    {
        const u64* awp = (const u64*)(s_misc + 128);
        u64 ata = 0ull, atb = 0ull;
#pragma unroll
        for (int q = 0; q < 16; q++) {
            u64 w = awp[q];
            FMA2(ata, m2a[q], w, ata);
            FMA2(atb, m2b[q], w, atb);
        }
        float a0, a1;
        UNPK2(a0, a1, ata);
        float atta = sigf(a0 + a1 + s_ab);
        UNPK2(a0, a1, atb);
        float attb = sigf(a0 + a1 + s_ab);
        u64 pa, pb;
        PACK2(pa, atta, atta);
        PACK2(pb, attb, attb);
#pragma unroll
        for (int q = 0; q < 16; q++) {
            MUL2(m2a[q], m2a[q], pa);
            MUL2(m2b[q], m2b[q], pb);
        }
    }

    // ---- coord head, interleaved: weights loaded once for both edges ----
    float transa, transb;
    {
        u64 c2a[16], c2b[16];
        const ulonglong2* cb = (const ulonglong2*)(s_misc + 96);
#pragma unroll
        for (int q = 0; q < 8; q++) {
            ulonglong2 v = cb[q];
            c2a[2*q] = v.x;  c2a[2*q+1] = v.y;
            c2b[2*q] = v.x;  c2b[2*q+1] = v.y;
        }
#pragma unroll 4
        for (int fp = 0; fp < 16; fp++) {
            float ma0, ma1, mb0, mb1;
            UNPK2(ma0, ma1, m2a[fp]);
            UNPK2(mb0, mb1, m2b[fp]);
            u64 pa0, pa1, pb0, pb1;
            PACK2(pa0, ma0, ma0); PACK2(pa1, ma1, ma1);
            PACK2(pb0, mb0, mb0); PACK2(pb1, mb1, mb1);
            const ulonglong2* wr = (const ulonglong2*)(s_c1 + (2*fp)*HH);
#pragma unroll
            for (int q = 0; q < 8; q++) {
                ulonglong2 wa = wr[q], wb = wr[q+8];
                FMA2(c2a[2*q],   pa0, wa.x, c2a[2*q]);
                FMA2(c2a[2*q+1], pa0, wa.y, c2a[2*q+1]);
                FMA2(c2a[2*q],   pa1, wb.x, c2a[2*q]);
                FMA2(c2a[2*q+1], pa1, wb.y, c2a[2*q+1]);
                FMA2(c2b[2*q],   pb0, wa.x, c2b[2*q]);
                FMA2(c2b[2*q+1], pb0, wa.y, c2b[2*q+1]);
                FMA2(c2b[2*q],   pb1, wb.x, c2b[2*q]);
                FMA2(c2b[2*q+1], pb1, wb.y, c2b[2*q+1]);
            }
        }
        float acca = 0.0f, accb = 0.0f;
#pragma unroll
        for (int q = 0; q < 16; q++) {
            float c0, c1v;
            UNPK2(c0, c1v, c2a[q]);
            acca += siluf(c0)  * s_misc[160 + 2*q];
            acca += siluf(c1v) * s_misc[160 + 2*q + 1];
            UNPK2(c0, c1v, c2b[q]);
            accb += siluf(c0)  * s_misc[160 + 2*q];
            accb += siluf(c1v) * s_misc[160 + 2*q + 1];
        }
        transa = tanhf(acca);
        transb = tanhf(accb);
    }

    float valida = (j == i0) ? 0.0f : 1.0f;
    float validb = (j == i1) ? 0.0f : 1.0f;
    float coefa = valida * __fdividef(transa, da + 1.0f);
    float coefb = validb * __fdividef(transb, db + 1.0f);

    // ---- coord reductions (both edges) ----
    {
        float x0 = rxa*coefa, x1 = rya*coefa, x2 = rza*coefa;
        float y0 = rxb*coefb, y1 = ryb*coefb, y2 = rzb*coefb;
#pragma unroll
        for (int off = 16; off > 0; off >>= 1) {
            x0 += __shfl_xor_sync(0xffffffffu, x0, off);
            x1 += __shfl_xor_sync(0xffffffffu, x1, off);
            x2 += __shfl_xor_sync(0xffffffffu, x2, off);
            y0 += __shfl_xor_sync(0xffffffffu, y0, off);
            y1 += __shfl_xor_sync(0xffffffffu, y1, off);
            y2 += __shfl_xor_sync(0xffffffffu, y2, off);
        }
        if (lane == 0) {
            s_xp[0][warp][0] = x0; s_xp[0][warp][1] = x1; s_xp[0][warp][2] = x2;
            s_xp[1][warp][0] = y0; s_xp[1][warp][1] = y1; s_xp[1][warp][2] = y2;
        }
    }

    // ---- butterfly vector reduce of m over lanes, edge a then edge b ----
    {
        float mm[FF];
#pragma unroll
        for (int q = 0; q < 16; q++) UNPK2(mm[2*q], mm[2*q+1], m2a[q]);
#pragma unroll
        for (int f = 0; f < FF; f++) mm[f] *= valida;
#pragma unroll
        for (int off = 16, nh = 16; off > 0; off >>= 1, nh >>= 1) {
            bool hi = (lane & off);
#pragma unroll
            for (int tt = 0; tt < 16; tt++) {
                if (tt < nh) {
                    float kept = hi ? mm[nh + tt] : mm[tt];
                    float sent = hi ? mm[tt]      : mm[nh + tt];
                    float recv = __shfl_xor_sync(0xffffffffu, sent, off);
                    mm[tt] = kept + recv;
                }
            }
        }
        s_part[0][warp][lane] = mm[0];
#pragma unroll
        for (int q = 0; q < 16; q++) UNPK2(mm[2*q], mm[2*q+1], m2b[q]);
#pragma unroll
        for (int f = 0; f < FF; f++) mm[f] *= validb;
#pragma unroll
        for (int off = 16, nh = 16; off > 0; off >>= 1, nh >>= 1) {
            bool hi = (lane & off);
#pragma unroll
            for (int tt = 0; tt < 16; tt++) {
                if (tt < nh) {
                    float kept = hi ? mm[nh + tt] : mm[tt];
                    float sent = hi ? mm[tt]      : mm[nh + tt];
                    float recv = __shfl_xor_sync(0xffffffffu, sent, off);
                    mm[tt] = kept + recv;
                }
            }
        }
        s_part[1][warp][lane] = mm[0];
    }
    __syncthreads();

    // ---- tail: warp 0 -> node i0, warp 1 -> node i1 ----
    if (warp < 2) {
        int e = warp;
        int node = b*NP + i0 + e;
        int f = lane;
        if (f < 3) {
            float xs = s_xp[e][0][f] + s_xp[e][1][f] + s_xp[e][2][f] + s_xp[e][3][f];
            x_out[b*DIM + (i0+e)*ND + f] = s_xi[e][f] + xs * 5.0f;   // COORDS_RANGE
        }
        float mi = s_part[e][0][f] + s_part[e][1][f] + s_part[e][2][f] + s_part[e][3][f];
        float hv = h[node*FF + f];
        float acc = n_b1[f];
#pragma unroll
        for (int k = 0; k < FF; k++)
            acc += __shfl_sync(0xffffffffu, hv, k) * n_w1[k*HH + f];
#pragma unroll
        for (int k = 0; k < FF; k++)
            acc += __shfl_sync(0xffffffffu, mi, k) * n_w1[(FF + k)*HH + f];
        float tt2 = siluf(acc);
        float acc2 = n_b2[f];
#pragma unroll
        for (int k = 0; k < HH; k++)
            acc2 += __shfl_sync(0xffffffffu, tt2, k) * n_w2[k*FF + f];
        h_out[node*FF + f] = hv + acc2;
    }
}

// ---------------------------------------------------------------------------
extern "C" void kernel_launch(void* const* d_in, const int* in_sizes, int n_in,
                              void* d_out, int out_size)
{
    const float* x        = (const float*)d_in[0];
    const float* h        = (const float*)d_in[1];
    const float* d_static = (const float*)d_in[2];
    const float* e_w1     = (const float*)d_in[3];
    const float* e_b1     = (const float*)d_in[4];
    const float* e_w2     = (const float*)d_in[5];
    const float* e_b2     = (const float*)d_in[6];
    const float* n_w1     = (const float*)d_in[7];
    const float* n_b1     = (const float*)d_in[8];
    const float* n_w2     = (const float*)d_in[9];
    const float* n_b2     = (const float*)d_in[10];
    const float* c_w1     = (const float*)d_in[11];
    const float* c_b1     = (const float*)d_in[12];
    const float* c_w2     = (const float*)d_in[13];
    const float* a_w      = (const float*)d_in[14];
    const float* a_b      = (const float*)d_in[15];

    float* out   = (float*)d_out;
    float* x_out = out;                 // B*DIM floats
    float* h_out = out + BB*DIM;        // B*NP*FF floats

    prenode_kernel<<<NNODE/4, 128>>>(h, e_w1, e_b1);
    edge_kernel<<<BB*NP/2, 128>>>(x, d_static, e_w1, e_w2, e_b2,
                                  c_w1, c_b1, c_w2, a_w, a_b,
                                  h, n_w1, n_b1, n_w2, n_b2,
                                  x_out, h_out);
}